// round 14
// baseline (speedup 1.0000x reference)
#include <cuda_runtime.h>
#include <math.h>

// ---------------- problem constants ----------------
#define D_MODEL  1024
#define NHEADS   16
#define HDIM     64
#define NTOK     2048
#define BATCH    2
#define MROWS    (BATCH*NTOK)       // 4096
#define QKVCOLS  (3*D_MODEL)        // 3072

// Q prescale: (1/8) * log2(e)  — scores land in log2 domain
#define QSCALE 0.18033688011112042f

// ---------------- scratch (tf32 bit patterns) ----------------
__device__ unsigned g_qkv[3*BATCH*NHEADS*NTOK*HDIM]; // Q (natural rows, d-perm, prescaled), K (natural rows, kk-interleaved d)
__device__ uint2    g_v2 [BATCH*NHEADS*1024*64];     // V pairs: [b,h][t>>1][d] = (V[2i][d], V[2i+1][d])
__device__ unsigned g_att[MROWS*D_MODEL];            // flash out, d-perm tf32
__device__ unsigned g_xt [MROWS*D_MODEL];            // X tf32, d-perm
__device__ unsigned g_wqi[(D_MODEL/8*4)*(QKVCOLS*2)]; // w_qkv tf32, k-pair interleaved
__device__ unsigned g_wpi[(D_MODEL/8*4)*(D_MODEL*2)]; // w_proj tf32, k-pair interleaved
__device__ float g_cos[NTOK*HDIM];
__device__ float g_sin[NTOK*HDIM];
__device__ float g_xs [NTOK*HDIM];

// ---------------- helpers ----------------
__device__ __forceinline__ unsigned f2tf(float f) {
    unsigned u;
    asm("cvt.rna.tf32.f32 %0, %1;" : "=r"(u) : "f"(f));
    return u;
}
__device__ __forceinline__ void mma8(float c[4], const unsigned a[4], unsigned b0, unsigned b1) {
    asm("mma.sync.aligned.m16n8k8.row.col.f32.tf32.tf32.f32 "
        "{%0,%1,%2,%3},{%4,%5,%6,%7},{%8,%9},{%0,%1,%2,%3};"
        : "+f"(c[0]), "+f"(c[1]), "+f"(c[2]), "+f"(c[3])
        : "r"(a[0]), "r"(a[1]), "r"(a[2]), "r"(a[3]), "r"(b0), "r"(b1));
}
__device__ __forceinline__ void cpa16(unsigned dst, const void* src) {
    asm volatile("cp.async.cg.shared.global [%0], [%1], 16;" :: "r"(dst), "l"(src));
}
__device__ __forceinline__ void cpa_commit() {
    asm volatile("cp.async.commit_group;");
}
template<int N>
__device__ __forceinline__ void cpa_wait() {
    asm volatile("cp.async.wait_group %0;" :: "n"(N));
}

// ============================================================
// Kernel 1: xpos/ND-RoPE tables (fp64, matches numpy ref)
// ============================================================
__global__ void rope_tables_kernel() {
    int idx = blockIdx.x * blockDim.x + threadIdx.x;
    if (idx >= NTOK*HDIM) return;
    int n = idx >> 6;
    int d = idx & 63;
    int axis = d >> 5;
    int jj   = d & 31;
    int p    = jj >> 1;
    double t, half;
    if (axis == 0) { t = (double)(n >> 6); half = 16.0; }
    else           { t = (double)(n & 63); half = 32.0; }
    double inv_freq = pow(10000.0, -((double)(2*p)) / 32.0);
    double f  = t * inv_freq;
    double sbase = ((double)(2*p) + 0.4*32.0) / (1.4*32.0);
    double power = (t - half) / 64.0;
    double sc = pow(sbase, power);
    g_cos[idx] = (float)cos(f);
    g_sin[idx] = (float)sin(f);
    g_xs [idx] = (float)sc;
}

// ============================================================
// Kernel 1b: preconvert X (d-perm) and weights (k-pair interleaved)
// ============================================================
__global__ void preconvert_kernel(const float* __restrict__ X,
                                  const float* __restrict__ Wq,
                                  const float* __restrict__ Wp) {
    const int NX  = MROWS*D_MODEL/4;
    const int NQ  = (D_MODEL/8*4)*(QKVCOLS/4);
    const int NP  = (D_MODEL/8*4)*(D_MODEL/4);
    int i = blockIdx.x * blockDim.x + threadIdx.x;
    if (i < NX) {
        float4 v = ((const float4*)X)[i];
        int e = i << 2;
        int off = (e & ~7) + ((e & 4) >> 2);
        g_xt[off+0] = f2tf(v.x);
        g_xt[off+2] = f2tf(v.y);
        g_xt[off+4] = f2tf(v.z);
        g_xt[off+6] = f2tf(v.w);
    } else if (i < NX + NQ) {
        int j = i - NX;
        int prow = j / (QKVCOLS/4);
        int cg   = (j - prow*(QKVCOLS/4)) << 2;
        int k    = ((prow >> 2) << 3) + (prow & 3);
        float4 v0 = *(const float4*)(Wq + (size_t)k*QKVCOLS + cg);
        float4 v1 = *(const float4*)(Wq + (size_t)(k+4)*QKVCOLS + cg);
        unsigned* d = &g_wqi[(size_t)prow*(QKVCOLS*2) + cg*2];
        uint4 u0; u0.x=f2tf(v0.x); u0.y=f2tf(v1.x); u0.z=f2tf(v0.y); u0.w=f2tf(v1.y);
        uint4 u1; u1.x=f2tf(v0.z); u1.y=f2tf(v1.z); u1.z=f2tf(v0.w); u1.w=f2tf(v1.w);
        *(uint4*)(d)   = u0;
        *(uint4*)(d+4) = u1;
    } else {
        int j = i - NX - NQ;
        if (j < NP) {
            int prow = j / (D_MODEL/4);
            int cg   = (j - prow*(D_MODEL/4)) << 2;
            int k    = ((prow >> 2) << 3) + (prow & 3);
            float4 v0 = *(const float4*)(Wp + (size_t)k*D_MODEL + cg);
            float4 v1 = *(const float4*)(Wp + (size_t)(k+4)*D_MODEL + cg);
            unsigned* d = &g_wpi[(size_t)prow*(D_MODEL*2) + cg*2];
            uint4 u0; u0.x=f2tf(v0.x); u0.y=f2tf(v1.x); u0.z=f2tf(v0.y); u0.w=f2tf(v1.y);
            uint4 u1; u1.x=f2tf(v0.z); u1.y=f2tf(v1.z); u1.z=f2tf(v0.w); u1.w=f2tf(v1.w);
            *(uint4*)(d)   = u0;
            *(uint4*)(d+4) = u1;
        }
    }
}

// ============================================================
// Kernel 2: TF32 GEMM, 3-stage cp.async, ONE barrier per k-iter
//   (R10 configuration: QKV TM=128, proj TM=64)
// ============================================================
#define AS_STR 40
#define BS_STR 264
#define GEMM_SMEM(TM) ((3*(TM)*AS_STR + 3*16*BS_STR)*4)

template<int NC, bool QKV, int TM>
__global__ __launch_bounds__(256, 2) void gemm_tf32_kernel(
    const float* __restrict__ bias, float* __restrict__ out)
{
    constexpr int MI = TM/32;
    extern __shared__ unsigned gsm_u[];
    unsigned* As = gsm_u;                    // [3][TM][AS_STR]
    unsigned* Bs = gsm_u + 3*TM*AS_STR;      // [3][16][BS_STR]

    const unsigned* Ap = QKV ? g_xt : g_att;
    const unsigned* Bp = QKV ? g_wqi : g_wpi;

    int tid = threadIdx.x;
    int lane = tid & 31, warp = tid >> 5;
    int lq = lane >> 2, lr = lane & 3;
    int wm = (warp >> 2) * (TM/2);
    int wn = (warp & 3) * 32;
    int bm = blockIdx.y * TM, bn = blockIdx.x * 128;

    float acc[MI][4][4];
#pragma unroll
    for (int mi = 0; mi < MI; mi++)
#pragma unroll
        for (int ni = 0; ni < 4; ni++)
#pragma unroll
            for (int r = 0; r < 4; r++) acc[mi][ni][r] = 0.f;

    int ar = tid >> 3, ac = (tid & 7) << 2;

    unsigned sA = (unsigned)__cvta_generic_to_shared(As);
    unsigned sB = (unsigned)__cvta_generic_to_shared(Bs);

    auto issue = [&](int stage, int k0) {
        unsigned dA = sA + (unsigned)(stage*TM*AS_STR)*4;
        unsigned dB = sB + (unsigned)(stage*16*BS_STR)*4;
#pragma unroll
        for (int p = 0; p < MI; p++)
            cpa16(dA + (unsigned)((ar + p*32)*AS_STR + ac)*4,
                  Ap + (size_t)(bm + ar + p*32)*1024 + k0 + ac);
#pragma unroll
        for (int p = 0; p < 4; p++) {
            int idx = p*256 + tid;
            int row = idx >> 6, c = (idx & 63) << 2;
            cpa16(dB + (unsigned)(row*BS_STR + c)*4,
                  Bp + (size_t)((k0>>1) + row)*(NC*2) + bn*2 + c);
        }
        cpa_commit();
    };

    issue(0, 0);
    issue(1, 32);

    const int NIT = 1024/32;
    int cur = 0;
    for (int it = 0; it < NIT; it++) {
        if (it < NIT-1) cpa_wait<1>(); else cpa_wait<0>();
        __syncthreads();
        if (it + 2 < NIT) {
            int nxt = cur + 2; if (nxt >= 3) nxt -= 3;
            issue(nxt, (it+2)*32);
        }

        const unsigned* Af = As + cur*TM*AS_STR;
        const unsigned* Bf = Bs + cur*16*BS_STR;
#pragma unroll
        for (int kk = 0; kk < 4; kk++) {
            unsigned af[MI][4];
            uint2 bf[4];
#pragma unroll
            for (int mi = 0; mi < MI; mi++) {
                int r = wm + mi*16 + lq;
                uint2 u0 = *(const uint2*)&Af[r*AS_STR + kk*8 + 2*lr];
                uint2 u1 = *(const uint2*)&Af[(r+8)*AS_STR + kk*8 + 2*lr];
                af[mi][0] = u0.x; af[mi][1] = u1.x;
                af[mi][2] = u0.y; af[mi][3] = u1.y;
            }
#pragma unroll
            for (int ni = 0; ni < 4; ni++)
                bf[ni] = *(const uint2*)&Bf[(kk*4 + lr)*BS_STR + (wn + ni*8 + lq)*2];
#pragma unroll
            for (int mi = 0; mi < MI; mi++)
#pragma unroll
                for (int ni = 0; ni < 4; ni++)
                    mma8(acc[mi][ni], af[mi], bf[ni].x, bf[ni].y);
        }
        if (++cur == 3) cur = 0;
    }

    // ---- epilogue ----
#pragma unroll
    for (int mi = 0; mi < MI; mi++) {
#pragma unroll
        for (int ni = 0; ni < 4; ni++) {
            int col = bn + wn + ni*8 + 2*lr;
            float bz0 = bias[col], bz1 = bias[col+1];
            int rA = bm + wm + mi*16 + lq;
            int rB = rA + 8;
            float a0 = acc[mi][ni][0] + bz0, a1 = acc[mi][ni][1] + bz1;
            float b0 = acc[mi][ni][2] + bz0, b1 = acc[mi][ni][3] + bz1;
            if (QKV) {
                int which = col >> 10, hh = (col >> 6) & 15, dd = col & 63;
                int bA = rA >> 11, nA = rA & 2047;
                int nB = nA + 8;
                if (which < 2) {   // rotate q,k
                    int tiA = (nA << 6) + dd, tiB = (nB << 6) + dd;
                    float cA = g_cos[tiA], sA_ = g_sin[tiA], xA = g_xs[tiA];
                    float cB = g_cos[tiB], sB_ = g_sin[tiB], xB = g_xs[tiB];
                    float y0 = a0*cA - a1*sA_, y1 = a1*cA + a0*sA_;
                    float z0 = b0*cB - b1*sB_, z1 = b1*cB + b0*sB_;
                    if (which == 0) {   // Q: *xs, prescale (1/8)*log2e, d-perm
                        a0 = y0*xA*QSCALE; a1 = y1*xA*QSCALE;
                        b0 = z0*xB*QSCALE; b1 = z1*xB*QSCALE;
                        int p0 = (dd & ~7) + (((lr & 1) << 2) | (lr >> 1));
                        size_t qA = ((size_t)((0 + bA)*16 + hh)*2048 + nA)*64;
                        size_t qB = ((size_t)((0 + bA)*16 + hh)*2048 + nB)*64;
                        g_qkv[qA + p0]     = f2tf(a0);
                        g_qkv[qA + p0 + 2] = f2tf(a1);
                        g_qkv[qB + p0]     = f2tf(b0);
                        g_qkv[qB + p0 + 2] = f2tf(b1);
                    } else {            // K: /xs, natural rows, kk-interleaved d
                        a0 = y0/xA; a1 = y1/xA; b0 = z0/xB; b1 = z1/xB;
                        int bb   = 16*(dd >> 4) + 2*((dd >> 3) & 1);
                        int off0 = bb + 8*(lr & 1) + (lr >> 1);
                        size_t kA = ((size_t)((2 + bA)*16 + hh)*2048 + nA)*64;
                        size_t kB = ((size_t)((2 + bA)*16 + hh)*2048 + nB)*64;
                        g_qkv[kA + off0]     = f2tf(a0);
                        g_qkv[kA + off0 + 4] = f2tf(a1);
                        g_qkv[kB + off0]     = f2tf(b0);
                        g_qkv[kB + off0 + 4] = f2tf(b1);
                    }
                } else {                // V: (t,t+1) pair layout, scalar stores
                    unsigned* vh = (unsigned*)(g_v2 + (size_t)(bA*16 + hh)*1024*64);
                    unsigned wA = (unsigned)((nA >> 1)*128 + dd*2 + (nA & 1));
                    unsigned wB = (unsigned)((nB >> 1)*128 + dd*2 + (nB & 1));
                    vh[wA]     = f2tf(a0);
                    vh[wA + 2] = f2tf(a1);
                    vh[wB]     = f2tf(b0);
                    vh[wB + 2] = f2tf(b1);
                }
            } else {
                *(float2*)&out[(size_t)rA*NC + col] = make_float2(a0, a1);
                *(float2*)&out[(size_t)rB*NC + col] = make_float2(b0, b1);
            }
        }
    }
}

// ============================================================
// Kernel 3: flash attention — 4 warps x 32 q-rows, dual m-tile,
//   LDS.128 K frags, P in registers, exp2 softmax,
//   Q tile staged in SMEM (FIXED full-tile copy for 128 thr),
//   frags loaded per-kkp (unroll 1) to cap register pressure;
//   cp.async double-buffered K/V.
// ============================================================
#define KS_STR 80
#define VI_STR 136
#define FQ_STR 72
#define FLASH_SMEM ((2*64*KS_STR + 2*32*VI_STR + 128*FQ_STR)*4)   // 112640

__global__ __launch_bounds__(128, 2) void flash_tf32_kernel() {
    extern __shared__ unsigned sm_u[];
    unsigned* Ks = sm_u;                             // [2][64][80]
    unsigned* Vi = sm_u + 2*64*KS_STR;               // [2][32][136]
    unsigned* Qs = sm_u + 2*64*KS_STR + 2*32*VI_STR; // [128][72]

    int tid = threadIdx.x;
    int lane = tid & 31, warp = tid >> 5;   // 4 warps
    int lq = lane >> 2, lr = lane & 3;
    int qt = blockIdx.x, bh = blockIdx.y;
    int b = bh >> 4, h = bh & 15;
    int r0 = warp * 32;

    const unsigned* Qg = g_qkv + ((size_t)((0 + b)*16 + h))*NTOK*HDIM + (size_t)qt*128*HDIM;
    const unsigned* Kg = g_qkv + ((size_t)((2 + b)*16 + h))*NTOK*HDIM;
    const unsigned* Vg = (const unsigned*)(g_v2 + (size_t)(b*16 + h)*1024*64);

    unsigned sKs = (unsigned)__cvta_generic_to_shared(Ks);
    unsigned sVi = (unsigned)__cvta_generic_to_shared(Vi);

    auto issueKV = [&](int kt, int s) {
        const unsigned* kg = Kg + (size_t)kt*64*HDIM;
        const unsigned* vg = Vg + (size_t)kt*32*128;
#pragma unroll
        for (int p = 0; p < 8; p++) {
            int idx = p*128 + tid;
            int krow = idx >> 4, kc = (idx & 15) << 2;
            cpa16(sKs + (unsigned)((s*64 + krow)*KS_STR + kc)*4, kg + krow*64 + kc);
            int vrow = idx >> 5, vc = (idx & 31) << 2;
            cpa16(sVi + (unsigned)((s*32 + vrow)*VI_STR + vc)*4, vg + vrow*128 + vc);
        }
        cpa_commit();
    };

    issueKV(0, 0);
    issueKV(1, 1);

    // stage Q tile into smem — FULL tile with 128 threads:
    // 128 rows x 16 uint4 = 2048 copies = 16 passes x 128 threads
    {
#pragma unroll
        for (int p = 0; p < 16; p++) {
            int idx = p*128 + tid;               // 0..2047
            int row = idx >> 4;                  // 0..127
            int c4  = (idx & 15) << 2;           // 0..60
            *(uint4*)&Qs[row*FQ_STR + c4] = *(const uint4*)(Qg + (size_t)row*HDIM + c4);
        }
    }
    __syncthreads();

    float O[2][8][4];
    float mst[4] = {-1e30f, -1e30f, -1e30f, -1e30f};
    float lst[4] = {0.f, 0.f, 0.f, 0.f};
#pragma unroll
    for (int mt = 0; mt < 2; mt++)
#pragma unroll
        for (int n = 0; n < 8; n++)
#pragma unroll
            for (int r = 0; r < 4; r++) O[mt][n][r] = 0.f;

    int pp = ((lr & 1) << 2) | (lr >> 1);

    // per-lane Q smem row bases
    const unsigned* q00 = &Qs[(r0 + lq)*FQ_STR + 2*lr];
    const unsigned* q01 = &Qs[(r0 + lq + 8)*FQ_STR + 2*lr];
    const unsigned* q10 = &Qs[(r0 + 16 + lq)*FQ_STR + 2*lr];
    const unsigned* q11 = &Qs[(r0 + 24 + lq)*FQ_STR + 2*lr];

    const int NKT = NTOK/64;
    for (int kt = 0; kt < NKT; kt++) {
        int s = kt & 1;
        if (kt + 2 < NKT) cpa_wait<1>(); else cpa_wait<0>();
        __syncthreads();

        const unsigned* Kf = Ks + s*64*KS_STR;
        const unsigned* Vf = Vi + s*32*VI_STR;

        // ---- S = Q K^T : kkp outer, unroll 1 (Q frags transient) ----
        float s0[8][4], s1[8][4];
#pragma unroll
        for (int n = 0; n < 8; n++) {
            s0[n][0]=s0[n][1]=s0[n][2]=s0[n][3]=0.f;
            s1[n][0]=s1[n][1]=s1[n][2]=s1[n][3]=0.f;
        }
#pragma unroll 1
        for (int kkp = 0; kkp < 4; kkp++) {
            unsigned qa0[4], qa1[4], qa2[4], qa3[4];
            {
                uint2 a0 = *(const uint2*)(q00 + kkp*16);
                uint2 a1 = *(const uint2*)(q01 + kkp*16);
                uint2 a2 = *(const uint2*)(q00 + kkp*16 + 8);
                uint2 a3 = *(const uint2*)(q01 + kkp*16 + 8);
                qa0[0]=a0.x; qa0[1]=a1.x; qa0[2]=a0.y; qa0[3]=a1.y;   // mt0, kk=2kkp
                qa1[0]=a2.x; qa1[1]=a3.x; qa1[2]=a2.y; qa1[3]=a3.y;   // mt0, kk=2kkp+1
                uint2 c0 = *(const uint2*)(q10 + kkp*16);
                uint2 c1 = *(const uint2*)(q11 + kkp*16);
                uint2 c2 = *(const uint2*)(q10 + kkp*16 + 8);
                uint2 c3 = *(const uint2*)(q11 + kkp*16 + 8);
                qa2[0]=c0.x; qa2[1]=c1.x; qa2[2]=c0.y; qa2[3]=c1.y;   // mt1, kk=2kkp
                qa3[0]=c2.x; qa3[1]=c3.x; qa3[2]=c2.y; qa3[3]=c3.y;   // mt1, kk=2kkp+1
            }
#pragma unroll
            for (int n = 0; n < 8; n++) {
                uint4 kb = *(const uint4*)&Kf[(n*8 + lq)*KS_STR + 4*lr + kkp*16];
                mma8(s0[n], qa0, kb.x, kb.y);
                mma8(s0[n], qa1, kb.z, kb.w);
                mma8(s1[n], qa2, kb.x, kb.y);
                mma8(s1[n], qa3, kb.z, kb.w);
            }
        }

        // ---- online softmax in exp2 domain ----
        float mA=-1e30f, mB=-1e30f, mC=-1e30f, mD=-1e30f;
#pragma unroll
        for (int n = 0; n < 8; n++) {
            mA = fmaxf(mA, fmaxf(s0[n][0], s0[n][1]));
            mB = fmaxf(mB, fmaxf(s0[n][2], s0[n][3]));
            mC = fmaxf(mC, fmaxf(s1[n][0], s1[n][1]));
            mD = fmaxf(mD, fmaxf(s1[n][2], s1[n][3]));
        }
        mA = fmaxf(mA, __shfl_xor_sync(0xffffffffu, mA, 1));
        mA = fmaxf(mA, __shfl_xor_sync(0xffffffffu, mA, 2));
        mB = fmaxf(mB, __shfl_xor_sync(0xffffffffu, mB, 1));
        mB = fmaxf(mB, __shfl_xor_sync(0xffffffffu, mB, 2));
        mC = fmaxf(mC, __shfl_xor_sync(0xffffffffu, mC, 1));
        mC = fmaxf(mC, __shfl_xor_sync(0xffffffffu, mC, 2));
        mD = fmaxf(mD, __shfl_xor_sync(0xffffffffu, mD, 1));
        mD = fmaxf(mD, __shfl_xor_sync(0xffffffffu, mD, 2));
        float mnA = fmaxf(mst[0], mA), mnB = fmaxf(mst[1], mB);
        float mnC = fmaxf(mst[2], mC), mnD = fmaxf(mst[3], mD);
        float cA = exp2f(mst[0]-mnA), cB = exp2f(mst[1]-mnB);
        float cC = exp2f(mst[2]-mnC), cD = exp2f(mst[3]-mnD);
        float sA=0.f, sB=0.f, sC=0.f, sD=0.f;
#pragma unroll
        for (int n = 0; n < 8; n++) {
            s0[n][0] = exp2f(s0[n][0]-mnA); s0[n][1] = exp2f(s0[n][1]-mnA);
            s0[n][2] = exp2f(s0[n][2]-mnB); s0[n][3] = exp2f(s0[n][3]-mnB);
            s1[n][0] = exp2f(s1[n][0]-mnC); s1[n][1] = exp2f(s1[n][1]-mnC);
            s1[n][2] = exp2f(s1[n][2]-mnD); s1[n][3] = exp2f(s1[n][3]-mnD);
            sA += s0[n][0]+s0[n][1]; sB += s0[n][2]+s0[n][3];
            sC += s1[n][0]+s1[n][1]; sD += s1[n][2]+s1[n][3];
        }
        sA += __shfl_xor_sync(0xffffffffu, sA, 1);
        sA += __shfl_xor_sync(0xffffffffu, sA, 2);
        sB += __shfl_xor_sync(0xffffffffu, sB, 1);
        sB += __shfl_xor_sync(0xffffffffu, sB, 2);
        sC += __shfl_xor_sync(0xffffffffu, sC, 1);
        sC += __shfl_xor_sync(0xffffffffu, sC, 2);
        sD += __shfl_xor_sync(0xffffffffu, sD, 1);
        sD += __shfl_xor_sync(0xffffffffu, sD, 2);
        lst[0] = lst[0]*cA + sA; mst[0] = mnA;
        lst[1] = lst[1]*cB + sB; mst[1] = mnB;
        lst[2] = lst[2]*cC + sC; mst[2] = mnC;
        lst[3] = lst[3]*cD + sD; mst[3] = mnD;
#pragma unroll
        for (int n = 0; n < 8; n++) {
            O[0][n][0] *= cA; O[0][n][1] *= cA;
            O[0][n][2] *= cB; O[0][n][3] *= cB;
            O[1][n][0] *= cC; O[1][n][1] *= cC;
            O[1][n][2] *= cD; O[1][n][3] *= cD;
        }

        // ---- O += P V : P A-frags direct from registers ----
#pragma unroll
        for (int kk = 0; kk < 8; kk++) {
            unsigned pa0[4], pa1[4];
            pa0[0] = f2tf(s0[kk][0]); pa0[1] = f2tf(s0[kk][2]);
            pa0[2] = f2tf(s0[kk][1]); pa0[3] = f2tf(s0[kk][3]);
            pa1[0] = f2tf(s1[kk][0]); pa1[1] = f2tf(s1[kk][2]);
            pa1[2] = f2tf(s1[kk][1]); pa1[3] = f2tf(s1[kk][3]);
            const unsigned* vrow = &Vf[(kk*4 + lr)*VI_STR];
#pragma unroll
            for (int n = 0; n < 8; n++) {
                uint2 vb = *(const uint2*)(vrow + (n*8 + lq)*2);
                mma8(O[0][n], pa0, vb.x, vb.y);
                mma8(O[1][n], pa1, vb.x, vb.y);
            }
        }

        __syncthreads();
        if (kt + 2 < NKT) issueKV(kt + 2, s);
    }

    // epilogue: normalize, tf32-round, d-perm store into g_att
    float iA = 1.f/lst[0], iB = 1.f/lst[1], iC = 1.f/lst[2], iD = 1.f/lst[3];
    int rowA = qt*128 + r0 + lq;
#pragma unroll
    for (int n = 0; n < 8; n++) {
        int col = h*HDIM + n*8 + pp;
        size_t b0 = (size_t)(b*NTOK + rowA)*D_MODEL + col;
        size_t b1 = (size_t)(b*NTOK + rowA + 8)*D_MODEL + col;
        size_t b2 = (size_t)(b*NTOK + rowA + 16)*D_MODEL + col;
        size_t b3 = (size_t)(b*NTOK + rowA + 24)*D_MODEL + col;
        g_att[b0]     = f2tf(O[0][n][0]*iA);
        g_att[b0 + 2] = f2tf(O[0][n][1]*iA);
        g_att[b1]     = f2tf(O[0][n][2]*iB);
        g_att[b1 + 2] = f2tf(O[0][n][3]*iB);
        g_att[b2]     = f2tf(O[1][n][0]*iC);
        g_att[b2 + 2] = f2tf(O[1][n][1]*iC);
        g_att[b3]     = f2tf(O[1][n][2]*iD);
        g_att[b3 + 2] = f2tf(O[1][n][3]*iD);
    }
}

// ============================================================
// launch
// ============================================================
extern "C" void kernel_launch(void* const* d_in, const int* in_sizes, int n_in,
                              void* d_out, int out_size) {
    const float* x      = (const float*)d_in[0];
    const float* w_qkv  = (const float*)d_in[1];
    const float* b_qkv  = (const float*)d_in[2];
    const float* w_proj = (const float*)d_in[3];
    const float* b_proj = (const float*)d_in[4];
    float* out = (float*)d_out;
    (void)in_sizes; (void)n_in; (void)out_size;

    rope_tables_kernel<<<(NTOK*HDIM)/256, 256>>>();

    const int NCONV = MROWS*D_MODEL/4 + (D_MODEL/8*4)*(QKVCOLS/4) + (D_MODEL/8*4)*(D_MODEL/4);
    preconvert_kernel<<<(NCONV + 255)/256, 256>>>(x, w_qkv, w_proj);

    cudaFuncSetAttribute(gemm_tf32_kernel<QKVCOLS, true, 128>,
                         cudaFuncAttributeMaxDynamicSharedMemorySize, GEMM_SMEM(128));
    gemm_tf32_kernel<QKVCOLS, true, 128>
        <<<dim3(QKVCOLS/128, MROWS/128), 256, GEMM_SMEM(128)>>>(b_qkv, nullptr);

    cudaFuncSetAttribute(flash_tf32_kernel,
                         cudaFuncAttributeMaxDynamicSharedMemorySize, FLASH_SMEM);
    flash_tf32_kernel<<<dim3(NTOK/128, BATCH*NHEADS), 128, FLASH_SMEM>>>();

    cudaFuncSetAttribute(gemm_tf32_kernel<D_MODEL, false, 64>,
                         cudaFuncAttributeMaxDynamicSharedMemorySize, GEMM_SMEM(64));
    gemm_tf32_kernel<D_MODEL, false, 64>
        <<<dim3(D_MODEL/128, MROWS/64), 256, GEMM_SMEM(64)>>>(b_proj, out);
}

// round 15
// speedup vs baseline: 1.0029x; 1.0029x over previous
#include <cuda_runtime.h>
#include <math.h>

// ---------------- problem constants ----------------
#define D_MODEL  1024
#define NHEADS   16
#define HDIM     64
#define NTOK     2048
#define BATCH    2
#define MROWS    (BATCH*NTOK)       // 4096
#define QKVCOLS  (3*D_MODEL)        // 3072

// Q prescale: (1/8) * log2(e)  — scores land in log2 domain
#define QSCALE 0.18033688011112042f

// ---------------- scratch (tf32 bit patterns) ----------------
__device__ unsigned g_qkv[3*BATCH*NHEADS*NTOK*HDIM]; // Q (natural rows, pair d-perm, prescaled), K (natural rows, kk-interleaved d)
__device__ uint2    g_v2 [BATCH*NHEADS*1024*64];     // V pairs: [b,h][t>>1][d] = (V[2i][d], V[2i+1][d])
__device__ unsigned g_att[MROWS*D_MODEL];            // flash out, A4-perm tf32
__device__ unsigned g_xt [MROWS*D_MODEL];            // X tf32, A4-perm
__device__ unsigned g_wqi[(D_MODEL/8*4)*(QKVCOLS*2)]; // w_qkv tf32, k-pair interleaved
__device__ unsigned g_wpi[(D_MODEL/8*4)*(D_MODEL*2)]; // w_proj tf32, k-pair interleaved
__device__ float g_cos[NTOK*HDIM];
__device__ float g_sin[NTOK*HDIM];
__device__ float g_xs [NTOK*HDIM];

// ---------------- helpers ----------------
__device__ __forceinline__ unsigned f2tf(float f) {
    unsigned u;
    asm("cvt.rna.tf32.f32 %0, %1;" : "=r"(u) : "f"(f));
    return u;
}
__device__ __forceinline__ void mma8(float c[4], const unsigned a[4], unsigned b0, unsigned b1) {
    asm("mma.sync.aligned.m16n8k8.row.col.f32.tf32.tf32.f32 "
        "{%0,%1,%2,%3},{%4,%5,%6,%7},{%8,%9},{%0,%1,%2,%3};"
        : "+f"(c[0]), "+f"(c[1]), "+f"(c[2]), "+f"(c[3])
        : "r"(a[0]), "r"(a[1]), "r"(a[2]), "r"(a[3]), "r"(b0), "r"(b1));
}
__device__ __forceinline__ void cpa16(unsigned dst, const void* src) {
    asm volatile("cp.async.cg.shared.global [%0], [%1], 16;" :: "r"(dst), "l"(src));
}
__device__ __forceinline__ void cpa_commit() {
    asm volatile("cp.async.commit_group;");
}
template<int N>
__device__ __forceinline__ void cpa_wait() {
    asm volatile("cp.async.wait_group %0;" :: "n"(N));
}

// ============================================================
// Kernel 1: xpos/ND-RoPE tables (fp64, matches numpy ref)
// ============================================================
__global__ void rope_tables_kernel() {
    int idx = blockIdx.x * blockDim.x + threadIdx.x;
    if (idx >= NTOK*HDIM) return;
    int n = idx >> 6;
    int d = idx & 63;
    int axis = d >> 5;
    int jj   = d & 31;
    int p    = jj >> 1;
    double t, half;
    if (axis == 0) { t = (double)(n >> 6); half = 16.0; }
    else           { t = (double)(n & 63); half = 32.0; }
    double inv_freq = pow(10000.0, -((double)(2*p)) / 32.0);
    double f  = t * inv_freq;
    double sbase = ((double)(2*p) + 0.4*32.0) / (1.4*32.0);
    double power = (t - half) / 64.0;
    double sc = pow(sbase, power);
    g_cos[idx] = (float)cos(f);
    g_sin[idx] = (float)sin(f);
    g_xs [idx] = (float)sc;
}

// ============================================================
// Kernel 1b: preconvert X (A4-perm) and weights (k-pair interleaved)
//   A4 perm within 16-block: logical j -> 4*(j&3) + (j>>2)
// ============================================================
__global__ void preconvert_kernel(const float* __restrict__ X,
                                  const float* __restrict__ Wq,
                                  const float* __restrict__ Wp) {
    const int NX  = MROWS*D_MODEL/4;
    const int NQ  = (D_MODEL/8*4)*(QKVCOLS/4);
    const int NP  = (D_MODEL/8*4)*(D_MODEL/4);
    int i = blockIdx.x * blockDim.x + threadIdx.x;
    if (i < NX) {
        float4 v = ((const float4*)X)[i];
        int e = i << 2;                 // 4-aligned logical index
        int m = (e >> 2) & 3;
        int base = e & ~15;
        g_xt[base + m]      = f2tf(v.x);   // j = 4m   -> pos m
        g_xt[base + 4 + m]  = f2tf(v.y);   // j = 4m+1 -> pos 4+m
        g_xt[base + 8 + m]  = f2tf(v.z);   // j = 4m+2 -> pos 8+m
        g_xt[base + 12 + m] = f2tf(v.w);   // j = 4m+3 -> pos 12+m
    } else if (i < NX + NQ) {
        int j = i - NX;
        int prow = j / (QKVCOLS/4);
        int cg   = (j - prow*(QKVCOLS/4)) << 2;
        int k    = ((prow >> 2) << 3) + (prow & 3);
        float4 v0 = *(const float4*)(Wq + (size_t)k*QKVCOLS + cg);
        float4 v1 = *(const float4*)(Wq + (size_t)(k+4)*QKVCOLS + cg);
        unsigned* d = &g_wqi[(size_t)prow*(QKVCOLS*2) + cg*2];
        uint4 u0; u0.x=f2tf(v0.x); u0.y=f2tf(v1.x); u0.z=f2tf(v0.y); u0.w=f2tf(v1.y);
        uint4 u1; u1.x=f2tf(v0.z); u1.y=f2tf(v1.z); u1.z=f2tf(v0.w); u1.w=f2tf(v1.w);
        *(uint4*)(d)   = u0;
        *(uint4*)(d+4) = u1;
    } else {
        int j = i - NX - NQ;
        if (j < NP) {
            int prow = j / (D_MODEL/4);
            int cg   = (j - prow*(D_MODEL/4)) << 2;
            int k    = ((prow >> 2) << 3) + (prow & 3);
            float4 v0 = *(const float4*)(Wp + (size_t)k*D_MODEL + cg);
            float4 v1 = *(const float4*)(Wp + (size_t)(k+4)*D_MODEL + cg);
            unsigned* d = &g_wpi[(size_t)prow*(D_MODEL*2) + cg*2];
            uint4 u0; u0.x=f2tf(v0.x); u0.y=f2tf(v1.x); u0.z=f2tf(v0.y); u0.w=f2tf(v1.y);
            uint4 u1; u1.x=f2tf(v0.z); u1.y=f2tf(v1.z); u1.z=f2tf(v0.w); u1.w=f2tf(v1.w);
            *(uint4*)(d)   = u0;
            *(uint4*)(d+4) = u1;
        }
    }
}

// ============================================================
// Kernel 2: TF32 GEMM, 2-stage cp.async (R8 loop),
//   A in A4-perm -> LDS.128 A-frags (2 kk per load), AS_STR=48
// ============================================================
#define AS_STR 48
#define BS_STR 264
#define GEMM_SMEM(TM) ((2*(TM)*AS_STR + 2*16*BS_STR)*4)

template<int NC, bool QKV, int TM>
__global__ __launch_bounds__(256, 2) void gemm_tf32_kernel(
    const float* __restrict__ bias, float* __restrict__ out)
{
    constexpr int MI = TM/32;
    extern __shared__ unsigned gsm_u[];
    unsigned* As = gsm_u;                    // [2][TM][48]
    unsigned* Bs = gsm_u + 2*TM*AS_STR;      // [2][16][264]

    const unsigned* Ap = QKV ? g_xt : g_att;
    const unsigned* Bp = QKV ? g_wqi : g_wpi;

    int tid = threadIdx.x;
    int lane = tid & 31, warp = tid >> 5;
    int lq = lane >> 2, lr = lane & 3;
    int wm = (warp >> 2) * (TM/2);
    int wn = (warp & 3) * 32;
    int bm = blockIdx.y * TM, bn = blockIdx.x * 128;

    float acc[MI][4][4];
#pragma unroll
    for (int mi = 0; mi < MI; mi++)
#pragma unroll
        for (int ni = 0; ni < 4; ni++)
#pragma unroll
            for (int r = 0; r < 4; r++) acc[mi][ni][r] = 0.f;

    int ar = tid >> 3, ac = (tid & 7) << 2;

    unsigned sA = (unsigned)__cvta_generic_to_shared(As);
    unsigned sB = (unsigned)__cvta_generic_to_shared(Bs);

    auto issue = [&](int stage, int k0) {
        unsigned dA = sA + (unsigned)(stage*TM*AS_STR)*4;
        unsigned dB = sB + (unsigned)(stage*16*BS_STR)*4;
#pragma unroll
        for (int p = 0; p < MI; p++)
            cpa16(dA + (unsigned)((ar + p*32)*AS_STR + ac)*4,
                  Ap + (size_t)(bm + ar + p*32)*1024 + k0 + ac);
#pragma unroll
        for (int p = 0; p < 4; p++) {
            int idx = p*256 + tid;
            int row = idx >> 6, c = (idx & 63) << 2;
            cpa16(dB + (unsigned)(row*BS_STR + c)*4,
                  Bp + (size_t)((k0>>1) + row)*(NC*2) + bn*2 + c);
        }
        cpa_commit();
    };

    issue(0, 0);
    issue(1, 32);

    const int NIT = 1024/32;
    for (int it = 0; it < NIT; it++) {
        int cur = it & 1;
        if (it + 2 < NIT) cpa_wait<1>(); else cpa_wait<0>();
        __syncthreads();

        const unsigned* Af = As + cur*TM*AS_STR;
        const unsigned* Bf = Bs + cur*16*BS_STR;
#pragma unroll
        for (int kkp = 0; kkp < 2; kkp++) {
            uint4 ua[MI], ub[MI];
#pragma unroll
            for (int mi = 0; mi < MI; mi++) {
                int r = wm + mi*16 + lq;
                ua[mi] = *(const uint4*)&Af[r*AS_STR + kkp*16 + 4*lr];
                ub[mi] = *(const uint4*)&Af[(r+8)*AS_STR + kkp*16 + 4*lr];
            }
#pragma unroll
            for (int half = 0; half < 2; half++) {
                int kk = 2*kkp + half;
                uint2 bf[4];
#pragma unroll
                for (int ni = 0; ni < 4; ni++)
                    bf[ni] = *(const uint2*)&Bf[(kk*4 + lr)*BS_STR + (wn + ni*8 + lq)*2];
#pragma unroll
                for (int mi = 0; mi < MI; mi++) {
                    unsigned af[4];
                    if (half == 0) { af[0]=ua[mi].x; af[1]=ub[mi].x; af[2]=ua[mi].y; af[3]=ub[mi].y; }
                    else           { af[0]=ua[mi].z; af[1]=ub[mi].z; af[2]=ua[mi].w; af[3]=ub[mi].w; }
#pragma unroll
                    for (int ni = 0; ni < 4; ni++)
                        mma8(acc[mi][ni], af, bf[ni].x, bf[ni].y);
                }
            }
        }
        __syncthreads();
        if (it + 2 < NIT) issue(cur, (it+2)*32);
    }

    // ---- epilogue ----
#pragma unroll
    for (int mi = 0; mi < MI; mi++) {
#pragma unroll
        for (int ni = 0; ni < 4; ni++) {
            int col = bn + wn + ni*8 + 2*lr;
            float bz0 = bias[col], bz1 = bias[col+1];
            int rA = bm + wm + mi*16 + lq;
            int rB = rA + 8;
            float a0 = acc[mi][ni][0] + bz0, a1 = acc[mi][ni][1] + bz1;
            float b0 = acc[mi][ni][2] + bz0, b1 = acc[mi][ni][3] + bz1;
            if (QKV) {
                int which = col >> 10, hh = (col >> 6) & 15, dd = col & 63;
                int bA = rA >> 11, nA = rA & 2047;
                int nB = nA + 8;
                if (which < 2) {   // rotate q,k
                    int tiA = (nA << 6) + dd, tiB = (nB << 6) + dd;
                    float cA = g_cos[tiA], sA_ = g_sin[tiA], xA = g_xs[tiA];
                    float cB = g_cos[tiB], sB_ = g_sin[tiB], xB = g_xs[tiB];
                    float y0 = a0*cA - a1*sA_, y1 = a1*cA + a0*sA_;
                    float z0 = b0*cB - b1*sB_, z1 = b1*cB + b0*sB_;
                    if (which == 0) {   // Q: *xs, prescale (1/8)*log2e, pair d-perm
                        a0 = y0*xA*QSCALE; a1 = y1*xA*QSCALE;
                        b0 = z0*xB*QSCALE; b1 = z1*xB*QSCALE;
                        int p0 = (dd & ~7) + (((lr & 1) << 2) | (lr >> 1));
                        size_t qA = ((size_t)((0 + bA)*16 + hh)*2048 + nA)*64;
                        size_t qB = ((size_t)((0 + bA)*16 + hh)*2048 + nB)*64;
                        g_qkv[qA + p0]     = f2tf(a0);
                        g_qkv[qA + p0 + 2] = f2tf(a1);
                        g_qkv[qB + p0]     = f2tf(b0);
                        g_qkv[qB + p0 + 2] = f2tf(b1);
                    } else {            // K: /xs, natural rows, kk-interleaved d
                        a0 = y0/xA; a1 = y1/xA; b0 = z0/xB; b1 = z1/xB;
                        int bb   = 16*(dd >> 4) + 2*((dd >> 3) & 1);
                        int off0 = bb + 8*(lr & 1) + (lr >> 1);
                        size_t kA = ((size_t)((2 + bA)*16 + hh)*2048 + nA)*64;
                        size_t kB = ((size_t)((2 + bA)*16 + hh)*2048 + nB)*64;
                        g_qkv[kA + off0]     = f2tf(a0);
                        g_qkv[kA + off0 + 4] = f2tf(a1);
                        g_qkv[kB + off0]     = f2tf(b0);
                        g_qkv[kB + off0 + 4] = f2tf(b1);
                    }
                } else {                // V: (t,t+1) pair layout, scalar stores
                    unsigned* vh = (unsigned*)(g_v2 + (size_t)(bA*16 + hh)*1024*64);
                    unsigned wA = (unsigned)((nA >> 1)*128 + dd*2 + (nA & 1));
                    unsigned wB = (unsigned)((nB >> 1)*128 + dd*2 + (nB & 1));
                    vh[wA]     = f2tf(a0);
                    vh[wA + 2] = f2tf(a1);
                    vh[wB]     = f2tf(b0);
                    vh[wB + 2] = f2tf(b1);
                }
            } else {
                *(float2*)&out[(size_t)rA*NC + col] = make_float2(a0, a1);
                *(float2*)&out[(size_t)rB*NC + col] = make_float2(b0, b1);
            }
        }
    }
}

// ============================================================
// Kernel 3: flash attention — R10 version verbatim (211us),
//   epilogue writes g_att in A4-perm for the proj GEMM.
// ============================================================
#define KS_STR 80
#define VI_STR 136
#define FLASH_SMEM ((2*64*KS_STR + 2*32*VI_STR)*4)   // 75776

__global__ __launch_bounds__(128, 2) void flash_tf32_kernel() {
    extern __shared__ unsigned sm_u[];
    unsigned* Ks = sm_u;                 // [2][64][80]
    unsigned* Vi = sm_u + 2*64*KS_STR;   // [2][32][136]

    int tid = threadIdx.x;
    int lane = tid & 31, warp = tid >> 5;   // 4 warps
    int lq = lane >> 2, lr = lane & 3;
    int qt = blockIdx.x, bh = blockIdx.y;
    int b = bh >> 4, h = bh & 15;
    int r0 = warp * 32;

    const unsigned* Qg = g_qkv + ((size_t)((0 + b)*16 + h))*NTOK*HDIM + (size_t)qt*128*HDIM;
    const unsigned* Kg = g_qkv + ((size_t)((2 + b)*16 + h))*NTOK*HDIM;
    const unsigned* Vg = (const unsigned*)(g_v2 + (size_t)(b*16 + h)*1024*64);

    unsigned sKs = (unsigned)__cvta_generic_to_shared(Ks);
    unsigned sVi = (unsigned)__cvta_generic_to_shared(Vi);

    auto issueKV = [&](int kt, int s) {
        const unsigned* kg = Kg + (size_t)kt*64*HDIM;
        const unsigned* vg = Vg + (size_t)kt*32*128;
#pragma unroll
        for (int p = 0; p < 8; p++) {
            int idx = p*128 + tid;
            int krow = idx >> 4, kc = (idx & 15) << 2;
            cpa16(sKs + (unsigned)((s*64 + krow)*KS_STR + kc)*4, kg + krow*64 + kc);
            int vrow = idx >> 5, vc = (idx & 31) << 2;
            cpa16(sVi + (unsigned)((s*32 + vrow)*VI_STR + vc)*4, vg + vrow*128 + vc);
        }
        cpa_commit();
    };

    issueKV(0, 0);
    issueKV(1, 1);

    // Q fragments straight from gmem (persistent)
    unsigned qf[2][8][4];
#pragma unroll
    for (int mt = 0; mt < 2; mt++)
#pragma unroll
        for (int kk = 0; kk < 8; kk++) {
            uint2 u0 = *(const uint2*)(Qg + (size_t)(r0 + mt*16 + lq)*HDIM + kk*8 + 2*lr);
            uint2 u1 = *(const uint2*)(Qg + (size_t)(r0 + mt*16 + lq + 8)*HDIM + kk*8 + 2*lr);
            qf[mt][kk][0] = u0.x; qf[mt][kk][1] = u1.x;
            qf[mt][kk][2] = u0.y; qf[mt][kk][3] = u1.y;
        }

    float O[2][8][4];
    float mst[4] = {-1e30f, -1e30f, -1e30f, -1e30f};
    float lst[4] = {0.f, 0.f, 0.f, 0.f};
#pragma unroll
    for (int mt = 0; mt < 2; mt++)
#pragma unroll
        for (int n = 0; n < 8; n++)
#pragma unroll
            for (int r = 0; r < 4; r++) O[mt][n][r] = 0.f;

    const int NKT = NTOK/64;
    for (int kt = 0; kt < NKT; kt++) {
        int s = kt & 1;
        if (kt + 2 < NKT) cpa_wait<1>(); else cpa_wait<0>();
        __syncthreads();

        const unsigned* Kf = Ks + s*64*KS_STR;
        const unsigned* Vf = Vi + s*32*VI_STR;

        // ---- S = Q K^T (log2-domain scores), both m-tiles ----
        float s0[8][4], s1[8][4];
#pragma unroll
        for (int n = 0; n < 8; n++) {
            s0[n][0]=s0[n][1]=s0[n][2]=s0[n][3]=0.f;
            s1[n][0]=s1[n][1]=s1[n][2]=s1[n][3]=0.f;
            const unsigned* krow = &Kf[(n*8 + lq)*KS_STR + 4*lr];
#pragma unroll
            for (int kkp = 0; kkp < 4; kkp++) {
                uint4 kb = *(const uint4*)(krow + kkp*16);
                mma8(s0[n], qf[0][2*kkp],   kb.x, kb.y);
                mma8(s0[n], qf[0][2*kkp+1], kb.z, kb.w);
                mma8(s1[n], qf[1][2*kkp],   kb.x, kb.y);
                mma8(s1[n], qf[1][2*kkp+1], kb.z, kb.w);
            }
        }

        // ---- online softmax in exp2 domain ----
        float mA=-1e30f, mB=-1e30f, mC=-1e30f, mD=-1e30f;
#pragma unroll
        for (int n = 0; n < 8; n++) {
            mA = fmaxf(mA, fmaxf(s0[n][0], s0[n][1]));
            mB = fmaxf(mB, fmaxf(s0[n][2], s0[n][3]));
            mC = fmaxf(mC, fmaxf(s1[n][0], s1[n][1]));
            mD = fmaxf(mD, fmaxf(s1[n][2], s1[n][3]));
        }
        mA = fmaxf(mA, __shfl_xor_sync(0xffffffffu, mA, 1));
        mA = fmaxf(mA, __shfl_xor_sync(0xffffffffu, mA, 2));
        mB = fmaxf(mB, __shfl_xor_sync(0xffffffffu, mB, 1));
        mB = fmaxf(mB, __shfl_xor_sync(0xffffffffu, mB, 2));
        mC = fmaxf(mC, __shfl_xor_sync(0xffffffffu, mC, 1));
        mC = fmaxf(mC, __shfl_xor_sync(0xffffffffu, mC, 2));
        mD = fmaxf(mD, __shfl_xor_sync(0xffffffffu, mD, 1));
        mD = fmaxf(mD, __shfl_xor_sync(0xffffffffu, mD, 2));
        float mnA = fmaxf(mst[0], mA), mnB = fmaxf(mst[1], mB);
        float mnC = fmaxf(mst[2], mC), mnD = fmaxf(mst[3], mD);
        float cA = exp2f(mst[0]-mnA), cB = exp2f(mst[1]-mnB);
        float cC = exp2f(mst[2]-mnC), cD = exp2f(mst[3]-mnD);
        float sA=0.f, sB=0.f, sC=0.f, sD=0.f;
#pragma unroll
        for (int n = 0; n < 8; n++) {
            s0[n][0] = exp2f(s0[n][0]-mnA); s0[n][1] = exp2f(s0[n][1]-mnA);
            s0[n][2] = exp2f(s0[n][2]-mnB); s0[n][3] = exp2f(s0[n][3]-mnB);
            s1[n][0] = exp2f(s1[n][0]-mnC); s1[n][1] = exp2f(s1[n][1]-mnC);
            s1[n][2] = exp2f(s1[n][2]-mnD); s1[n][3] = exp2f(s1[n][3]-mnD);
            sA += s0[n][0]+s0[n][1]; sB += s0[n][2]+s0[n][3];
            sC += s1[n][0]+s1[n][1]; sD += s1[n][2]+s1[n][3];
        }
        sA += __shfl_xor_sync(0xffffffffu, sA, 1);
        sA += __shfl_xor_sync(0xffffffffu, sA, 2);
        sB += __shfl_xor_sync(0xffffffffu, sB, 1);
        sB += __shfl_xor_sync(0xffffffffu, sB, 2);
        sC += __shfl_xor_sync(0xffffffffu, sC, 1);
        sC += __shfl_xor_sync(0xffffffffu, sC, 2);
        sD += __shfl_xor_sync(0xffffffffu, sD, 1);
        sD += __shfl_xor_sync(0xffffffffu, sD, 2);
        lst[0] = lst[0]*cA + sA; mst[0] = mnA;
        lst[1] = lst[1]*cB + sB; mst[1] = mnB;
        lst[2] = lst[2]*cC + sC; mst[2] = mnC;
        lst[3] = lst[3]*cD + sD; mst[3] = mnD;
#pragma unroll
        for (int n = 0; n < 8; n++) {
            O[0][n][0] *= cA; O[0][n][1] *= cA;
            O[0][n][2] *= cB; O[0][n][3] *= cB;
            O[1][n][0] *= cC; O[1][n][1] *= cC;
            O[1][n][2] *= cD; O[1][n][3] *= cD;
        }

        // ---- O += P V : P A-frags direct from registers ----
#pragma unroll
        for (int kk = 0; kk < 8; kk++) {
            unsigned pa0[4], pa1[4];
            pa0[0] = f2tf(s0[kk][0]); pa0[1] = f2tf(s0[kk][2]);
            pa0[2] = f2tf(s0[kk][1]); pa0[3] = f2tf(s0[kk][3]);
            pa1[0] = f2tf(s1[kk][0]); pa1[1] = f2tf(s1[kk][2]);
            pa1[2] = f2tf(s1[kk][1]); pa1[3] = f2tf(s1[kk][3]);
            const unsigned* vrow = &Vf[(kk*4 + lr)*VI_STR];
#pragma unroll
            for (int n = 0; n < 8; n++) {
                uint2 vb = *(const uint2*)(vrow + (n*8 + lq)*2);
                mma8(O[0][n], pa0, vb.x, vb.y);
                mma8(O[1][n], pa1, vb.x, vb.y);
            }
        }

        __syncthreads();
        if (kt + 2 < NKT) issueKV(kt + 2, s);
    }

    // epilogue: normalize, tf32-round, A4-perm store into g_att
    // logical col d = h*64 + n*8 + (2lr + q), q in {0,1}
    // A4 pos = base16 + 4*(d16&3) + (d16>>2); pair (q=0,q=1) lands at off, off+4
    float iA = 1.f/lst[0], iB = 1.f/lst[1], iC = 1.f/lst[2], iD = 1.f/lst[3];
    int rowA = qt*128 + r0 + lq;
#pragma unroll
    for (int n = 0; n < 8; n++) {
        int base16 = h*HDIM + ((n >> 1) << 4);
        int off = 8*(lr & 1) + 2*(n & 1) + (lr >> 1);
        int col = base16 + off;
        size_t b0 = (size_t)(b*NTOK + rowA)*D_MODEL + col;
        size_t b1 = (size_t)(b*NTOK + rowA + 8)*D_MODEL + col;
        size_t b2 = (size_t)(b*NTOK + rowA + 16)*D_MODEL + col;
        size_t b3 = (size_t)(b*NTOK + rowA + 24)*D_MODEL + col;
        g_att[b0]     = f2tf(O[0][n][0]*iA);
        g_att[b0 + 4] = f2tf(O[0][n][1]*iA);
        g_att[b1]     = f2tf(O[0][n][2]*iB);
        g_att[b1 + 4] = f2tf(O[0][n][3]*iB);
        g_att[b2]     = f2tf(O[1][n][0]*iC);
        g_att[b2 + 4] = f2tf(O[1][n][1]*iC);
        g_att[b3]     = f2tf(O[1][n][2]*iD);
        g_att[b3 + 4] = f2tf(O[1][n][3]*iD);
    }
}

// ============================================================
// launch
// ============================================================
extern "C" void kernel_launch(void* const* d_in, const int* in_sizes, int n_in,
                              void* d_out, int out_size) {
    const float* x      = (const float*)d_in[0];
    const float* w_qkv  = (const float*)d_in[1];
    const float* b_qkv  = (const float*)d_in[2];
    const float* w_proj = (const float*)d_in[3];
    const float* b_proj = (const float*)d_in[4];
    float* out = (float*)d_out;
    (void)in_sizes; (void)n_in; (void)out_size;

    rope_tables_kernel<<<(NTOK*HDIM)/256, 256>>>();

    const int NCONV = MROWS*D_MODEL/4 + (D_MODEL/8*4)*(QKVCOLS/4) + (D_MODEL/8*4)*(D_MODEL/4);
    preconvert_kernel<<<(NCONV + 255)/256, 256>>>(x, w_qkv, w_proj);

    cudaFuncSetAttribute(gemm_tf32_kernel<QKVCOLS, true, 128>,
                         cudaFuncAttributeMaxDynamicSharedMemorySize, GEMM_SMEM(128));
    gemm_tf32_kernel<QKVCOLS, true, 128>
        <<<dim3(QKVCOLS/128, MROWS/128), 256, GEMM_SMEM(128)>>>(b_qkv, nullptr);

    cudaFuncSetAttribute(flash_tf32_kernel,
                         cudaFuncAttributeMaxDynamicSharedMemorySize, FLASH_SMEM);
    flash_tf32_kernel<<<dim3(NTOK/128, BATCH*NHEADS), 128, FLASH_SMEM>>>();

    cudaFuncSetAttribute(gemm_tf32_kernel<D_MODEL, false, 64>,
                         cudaFuncAttributeMaxDynamicSharedMemorySize, GEMM_SMEM(64));
    gemm_tf32_kernel<D_MODEL, false, 64>
        <<<dim3(D_MODEL/128, MROWS/64), 256, GEMM_SMEM(64)>>>(b_proj, out);
}

// round 16
// speedup vs baseline: 1.0507x; 1.0476x over previous
#include <cuda_runtime.h>
#include <math.h>

// ---------------- problem constants ----------------
#define D_MODEL  1024
#define NHEADS   16
#define HDIM     64
#define NTOK     2048
#define BATCH    2
#define MROWS    (BATCH*NTOK)       // 4096
#define QKVCOLS  (3*D_MODEL)        // 3072

// Q prescale: (1/8) * log2(e)  — scores land in log2 domain
#define QSCALE 0.18033688011112042f

// ---------------- scratch (tf32 bit patterns) ----------------
__device__ unsigned g_qkv[3*BATCH*NHEADS*NTOK*HDIM]; // Q (natural rows, d-perm, prescaled), K (natural rows, kk-interleaved d)
__device__ uint2    g_v2 [BATCH*NHEADS*1024*64];     // V pairs: [b,h][t>>1][d] = (V[2i][d], V[2i+1][d])
__device__ unsigned g_att[MROWS*D_MODEL];            // flash out, d-perm tf32
__device__ unsigned g_xt [MROWS*D_MODEL];            // X tf32, d-perm
__device__ unsigned g_wqi[(D_MODEL/8*4)*(QKVCOLS*2)]; // w_qkv tf32, k-pair interleaved
__device__ unsigned g_wpi[(D_MODEL/8*4)*(D_MODEL*2)]; // w_proj tf32, k-pair interleaved
__device__ float g_cos[NTOK*HDIM];
__device__ float g_sin[NTOK*HDIM];
__device__ float g_xs [NTOK*HDIM];
__device__ float g_xsi[NTOK*HDIM];   // 1/xs, precomputed in fp64

// ---------------- helpers ----------------
__device__ __forceinline__ unsigned f2tf(float f) {
    unsigned u;
    asm("cvt.rna.tf32.f32 %0, %1;" : "=r"(u) : "f"(f));
    return u;
}
__device__ __forceinline__ void mma8(float c[4], const unsigned a[4], unsigned b0, unsigned b1) {
    asm("mma.sync.aligned.m16n8k8.row.col.f32.tf32.tf32.f32 "
        "{%0,%1,%2,%3},{%4,%5,%6,%7},{%8,%9},{%0,%1,%2,%3};"
        : "+f"(c[0]), "+f"(c[1]), "+f"(c[2]), "+f"(c[3])
        : "r"(a[0]), "r"(a[1]), "r"(a[2]), "r"(a[3]), "r"(b0), "r"(b1));
}
__device__ __forceinline__ void cpa16(unsigned dst, const void* src) {
    asm volatile("cp.async.cg.shared.global [%0], [%1], 16;" :: "r"(dst), "l"(src));
}
__device__ __forceinline__ void cpa_commit() {
    asm volatile("cp.async.commit_group;");
}
template<int N>
__device__ __forceinline__ void cpa_wait() {
    asm volatile("cp.async.wait_group %0;" :: "n"(N));
}

// ============================================================
// Kernel 1: xpos/ND-RoPE tables (fp64, matches numpy ref)
// ============================================================
__global__ void rope_tables_kernel() {
    int idx = blockIdx.x * blockDim.x + threadIdx.x;
    if (idx >= NTOK*HDIM) return;
    int n = idx >> 6;
    int d = idx & 63;
    int axis = d >> 5;
    int jj   = d & 31;
    int p    = jj >> 1;
    double t, half;
    if (axis == 0) { t = (double)(n >> 6); half = 16.0; }
    else           { t = (double)(n & 63); half = 32.0; }
    double inv_freq = pow(10000.0, -((double)(2*p)) / 32.0);
    double f  = t * inv_freq;
    double sbase = ((double)(2*p) + 0.4*32.0) / (1.4*32.0);
    double power = (t - half) / 64.0;
    double sc = pow(sbase, power);
    g_cos[idx] = (float)cos(f);
    g_sin[idx] = (float)sin(f);
    g_xs [idx] = (float)sc;
    g_xsi[idx] = (float)(1.0 / sc);
}

// ============================================================
// Kernel 1b: preconvert X (d-perm) and weights (k-pair interleaved)
// ============================================================
__global__ void preconvert_kernel(const float* __restrict__ X,
                                  const float* __restrict__ Wq,
                                  const float* __restrict__ Wp) {
    const int NX  = MROWS*D_MODEL/4;
    const int NQ  = (D_MODEL/8*4)*(QKVCOLS/4);
    const int NP  = (D_MODEL/8*4)*(D_MODEL/4);
    int i = blockIdx.x * blockDim.x + threadIdx.x;
    if (i < NX) {
        float4 v = ((const float4*)X)[i];
        int e = i << 2;
        int off = (e & ~7) + ((e & 4) >> 2);
        g_xt[off+0] = f2tf(v.x);
        g_xt[off+2] = f2tf(v.y);
        g_xt[off+4] = f2tf(v.z);
        g_xt[off+6] = f2tf(v.w);
    } else if (i < NX + NQ) {
        int j = i - NX;
        int prow = j / (QKVCOLS/4);
        int cg   = (j - prow*(QKVCOLS/4)) << 2;
        int k    = ((prow >> 2) << 3) + (prow & 3);
        float4 v0 = *(const float4*)(Wq + (size_t)k*QKVCOLS + cg);
        float4 v1 = *(const float4*)(Wq + (size_t)(k+4)*QKVCOLS + cg);
        unsigned* d = &g_wqi[(size_t)prow*(QKVCOLS*2) + cg*2];
        uint4 u0; u0.x=f2tf(v0.x); u0.y=f2tf(v1.x); u0.z=f2tf(v0.y); u0.w=f2tf(v1.y);
        uint4 u1; u1.x=f2tf(v0.z); u1.y=f2tf(v1.z); u1.z=f2tf(v0.w); u1.w=f2tf(v1.w);
        *(uint4*)(d)   = u0;
        *(uint4*)(d+4) = u1;
    } else {
        int j = i - NX - NQ;
        if (j < NP) {
            int prow = j / (D_MODEL/4);
            int cg   = (j - prow*(D_MODEL/4)) << 2;
            int k    = ((prow >> 2) << 3) + (prow & 3);
            float4 v0 = *(const float4*)(Wp + (size_t)k*D_MODEL + cg);
            float4 v1 = *(const float4*)(Wp + (size_t)(k+4)*D_MODEL + cg);
            unsigned* d = &g_wpi[(size_t)prow*(D_MODEL*2) + cg*2];
            uint4 u0; u0.x=f2tf(v0.x); u0.y=f2tf(v1.x); u0.z=f2tf(v0.y); u0.w=f2tf(v1.y);
            uint4 u1; u1.x=f2tf(v0.z); u1.y=f2tf(v1.z); u1.z=f2tf(v0.w); u1.w=f2tf(v1.w);
            *(uint4*)(d)   = u0;
            *(uint4*)(d+4) = u1;
        }
    }
}

// ============================================================
// Kernel 2: TF32 GEMM, 3-stage cp.async, ONE barrier per k-iter
//   (R10 configuration: QKV TM=128, proj TM=64)
// ============================================================
#define AS_STR 40
#define BS_STR 264
#define GEMM_SMEM(TM) ((3*(TM)*AS_STR + 3*16*BS_STR)*4)

template<int NC, bool QKV, int TM>
__global__ __launch_bounds__(256, 2) void gemm_tf32_kernel(
    const float* __restrict__ bias, float* __restrict__ out)
{
    constexpr int MI = TM/32;
    extern __shared__ unsigned gsm_u[];
    unsigned* As = gsm_u;                    // [3][TM][AS_STR]
    unsigned* Bs = gsm_u + 3*TM*AS_STR;      // [3][16][BS_STR]

    const unsigned* Ap = QKV ? g_xt : g_att;
    const unsigned* Bp = QKV ? g_wqi : g_wpi;

    int tid = threadIdx.x;
    int lane = tid & 31, warp = tid >> 5;
    int lq = lane >> 2, lr = lane & 3;
    int wm = (warp >> 2) * (TM/2);
    int wn = (warp & 3) * 32;
    int bm = blockIdx.y * TM, bn = blockIdx.x * 128;

    float acc[MI][4][4];
#pragma unroll
    for (int mi = 0; mi < MI; mi++)
#pragma unroll
        for (int ni = 0; ni < 4; ni++)
#pragma unroll
            for (int r = 0; r < 4; r++) acc[mi][ni][r] = 0.f;

    int ar = tid >> 3, ac = (tid & 7) << 2;

    unsigned sA = (unsigned)__cvta_generic_to_shared(As);
    unsigned sB = (unsigned)__cvta_generic_to_shared(Bs);

    auto issue = [&](int stage, int k0) {
        unsigned dA = sA + (unsigned)(stage*TM*AS_STR)*4;
        unsigned dB = sB + (unsigned)(stage*16*BS_STR)*4;
#pragma unroll
        for (int p = 0; p < MI; p++)
            cpa16(dA + (unsigned)((ar + p*32)*AS_STR + ac)*4,
                  Ap + (size_t)(bm + ar + p*32)*1024 + k0 + ac);
#pragma unroll
        for (int p = 0; p < 4; p++) {
            int idx = p*256 + tid;
            int row = idx >> 6, c = (idx & 63) << 2;
            cpa16(dB + (unsigned)(row*BS_STR + c)*4,
                  Bp + (size_t)((k0>>1) + row)*(NC*2) + bn*2 + c);
        }
        cpa_commit();
    };

    issue(0, 0);
    issue(1, 32);

    const int NIT = 1024/32;
    int cur = 0;
    for (int it = 0; it < NIT; it++) {
        if (it < NIT-1) cpa_wait<1>(); else cpa_wait<0>();
        __syncthreads();
        if (it + 2 < NIT) {
            int nxt = cur + 2; if (nxt >= 3) nxt -= 3;
            issue(nxt, (it+2)*32);
        }

        const unsigned* Af = As + cur*TM*AS_STR;
        const unsigned* Bf = Bs + cur*16*BS_STR;
#pragma unroll
        for (int kk = 0; kk < 4; kk++) {
            unsigned af[MI][4];
            uint2 bf[4];
#pragma unroll
            for (int mi = 0; mi < MI; mi++) {
                int r = wm + mi*16 + lq;
                uint2 u0 = *(const uint2*)&Af[r*AS_STR + kk*8 + 2*lr];
                uint2 u1 = *(const uint2*)&Af[(r+8)*AS_STR + kk*8 + 2*lr];
                af[mi][0] = u0.x; af[mi][1] = u1.x;
                af[mi][2] = u0.y; af[mi][3] = u1.y;
            }
#pragma unroll
            for (int ni = 0; ni < 4; ni++)
                bf[ni] = *(const uint2*)&Bf[(kk*4 + lr)*BS_STR + (wn + ni*8 + lq)*2];
#pragma unroll
            for (int mi = 0; mi < MI; mi++)
#pragma unroll
                for (int ni = 0; ni < 4; ni++)
                    mma8(acc[mi][ni], af[mi], bf[ni].x, bf[ni].y);
        }
        if (++cur == 3) cur = 0;
    }

    // ---- epilogue ----
#pragma unroll
    for (int mi = 0; mi < MI; mi++) {
#pragma unroll
        for (int ni = 0; ni < 4; ni++) {
            int col = bn + wn + ni*8 + 2*lr;
            float bz0 = bias[col], bz1 = bias[col+1];
            int rA = bm + wm + mi*16 + lq;
            int rB = rA + 8;
            float a0 = acc[mi][ni][0] + bz0, a1 = acc[mi][ni][1] + bz1;
            float b0 = acc[mi][ni][2] + bz0, b1 = acc[mi][ni][3] + bz1;
            if (QKV) {
                int which = col >> 10, hh = (col >> 6) & 15, dd = col & 63;
                int bA = rA >> 11, nA = rA & 2047;
                int nB = nA + 8;
                if (which < 2) {   // rotate q,k
                    int tiA = (nA << 6) + dd, tiB = (nB << 6) + dd;
                    float cA = g_cos[tiA], sA_ = g_sin[tiA];
                    float cB = g_cos[tiB], sB_ = g_sin[tiB];
                    float y0 = a0*cA - a1*sA_, y1 = a1*cA + a0*sA_;
                    float z0 = b0*cB - b1*sB_, z1 = b1*cB + b0*sB_;
                    if (which == 0) {   // Q: *xs, prescale (1/8)*log2e, d-perm
                        float xA = g_xs[tiA], xB = g_xs[tiB];
                        a0 = y0*xA*QSCALE; a1 = y1*xA*QSCALE;
                        b0 = z0*xB*QSCALE; b1 = z1*xB*QSCALE;
                        int p0 = (dd & ~7) + (((lr & 1) << 2) | (lr >> 1));
                        size_t qA = ((size_t)((0 + bA)*16 + hh)*2048 + nA)*64;
                        size_t qB = ((size_t)((0 + bA)*16 + hh)*2048 + nB)*64;
                        g_qkv[qA + p0]     = f2tf(a0);
                        g_qkv[qA + p0 + 2] = f2tf(a1);
                        g_qkv[qB + p0]     = f2tf(b0);
                        g_qkv[qB + p0 + 2] = f2tf(b1);
                    } else {            // K: *(1/xs), natural rows, kk-interleaved d
                        float xiA = g_xsi[tiA], xiB = g_xsi[tiB];
                        a0 = y0*xiA; a1 = y1*xiA; b0 = z0*xiB; b1 = z1*xiB;
                        int bb   = 16*(dd >> 4) + 2*((dd >> 3) & 1);
                        int off0 = bb + 8*(lr & 1) + (lr >> 1);
                        size_t kA = ((size_t)((2 + bA)*16 + hh)*2048 + nA)*64;
                        size_t kB = ((size_t)((2 + bA)*16 + hh)*2048 + nB)*64;
                        g_qkv[kA + off0]     = f2tf(a0);
                        g_qkv[kA + off0 + 4] = f2tf(a1);
                        g_qkv[kB + off0]     = f2tf(b0);
                        g_qkv[kB + off0 + 4] = f2tf(b1);
                    }
                } else {                // V: (t,t+1) pair layout, scalar stores
                    unsigned* vh = (unsigned*)(g_v2 + (size_t)(bA*16 + hh)*1024*64);
                    unsigned wA = (unsigned)((nA >> 1)*128 + dd*2 + (nA & 1));
                    unsigned wB = (unsigned)((nB >> 1)*128 + dd*2 + (nB & 1));
                    vh[wA]     = f2tf(a0);
                    vh[wA + 2] = f2tf(a1);
                    vh[wB]     = f2tf(b0);
                    vh[wB + 2] = f2tf(b1);
                }
            } else {
                *(float2*)&out[(size_t)rA*NC + col] = make_float2(a0, a1);
                *(float2*)&out[(size_t)rB*NC + col] = make_float2(b0, b1);
            }
        }
    }
}

// ============================================================
// Kernel 3: flash attention — R10 version verbatim (211us):
//   4 warps x 32 q-rows, dual m-tile, LDS.128 K frags,
//   persistent Q frags, P in registers, exp2 softmax,
//   cp.async double-buffered K/V.
// ============================================================
#define KS_STR 80
#define VI_STR 136
#define FLASH_SMEM ((2*64*KS_STR + 2*32*VI_STR)*4)   // 75776

__global__ __launch_bounds__(128, 2) void flash_tf32_kernel() {
    extern __shared__ unsigned sm_u[];
    unsigned* Ks = sm_u;                 // [2][64][80]
    unsigned* Vi = sm_u + 2*64*KS_STR;   // [2][32][136]

    int tid = threadIdx.x;
    int lane = tid & 31, warp = tid >> 5;   // 4 warps
    int lq = lane >> 2, lr = lane & 3;
    int qt = blockIdx.x, bh = blockIdx.y;
    int b = bh >> 4, h = bh & 15;
    int r0 = warp * 32;

    const unsigned* Qg = g_qkv + ((size_t)((0 + b)*16 + h))*NTOK*HDIM + (size_t)qt*128*HDIM;
    const unsigned* Kg = g_qkv + ((size_t)((2 + b)*16 + h))*NTOK*HDIM;
    const unsigned* Vg = (const unsigned*)(g_v2 + (size_t)(b*16 + h)*1024*64);

    unsigned sKs = (unsigned)__cvta_generic_to_shared(Ks);
    unsigned sVi = (unsigned)__cvta_generic_to_shared(Vi);

    auto issueKV = [&](int kt, int s) {
        const unsigned* kg = Kg + (size_t)kt*64*HDIM;
        const unsigned* vg = Vg + (size_t)kt*32*128;
#pragma unroll
        for (int p = 0; p < 8; p++) {
            int idx = p*128 + tid;
            int krow = idx >> 4, kc = (idx & 15) << 2;
            cpa16(sKs + (unsigned)((s*64 + krow)*KS_STR + kc)*4, kg + krow*64 + kc);
            int vrow = idx >> 5, vc = (idx & 31) << 2;
            cpa16(sVi + (unsigned)((s*32 + vrow)*VI_STR + vc)*4, vg + vrow*128 + vc);
        }
        cpa_commit();
    };

    issueKV(0, 0);
    issueKV(1, 1);

    // Q fragments straight from gmem (persistent)
    unsigned qf[2][8][4];
#pragma unroll
    for (int mt = 0; mt < 2; mt++)
#pragma unroll
        for (int kk = 0; kk < 8; kk++) {
            uint2 u0 = *(const uint2*)(Qg + (size_t)(r0 + mt*16 + lq)*HDIM + kk*8 + 2*lr);
            uint2 u1 = *(const uint2*)(Qg + (size_t)(r0 + mt*16 + lq + 8)*HDIM + kk*8 + 2*lr);
            qf[mt][kk][0] = u0.x; qf[mt][kk][1] = u1.x;
            qf[mt][kk][2] = u0.y; qf[mt][kk][3] = u1.y;
        }

    float O[2][8][4];
    float mst[4] = {-1e30f, -1e30f, -1e30f, -1e30f};
    float lst[4] = {0.f, 0.f, 0.f, 0.f};
#pragma unroll
    for (int mt = 0; mt < 2; mt++)
#pragma unroll
        for (int n = 0; n < 8; n++)
#pragma unroll
            for (int r = 0; r < 4; r++) O[mt][n][r] = 0.f;

    int pp = ((lr & 1) << 2) | (lr >> 1);

    const int NKT = NTOK/64;
    for (int kt = 0; kt < NKT; kt++) {
        int s = kt & 1;
        if (kt + 2 < NKT) cpa_wait<1>(); else cpa_wait<0>();
        __syncthreads();

        const unsigned* Kf = Ks + s*64*KS_STR;
        const unsigned* Vf = Vi + s*32*VI_STR;

        // ---- S = Q K^T (log2-domain scores), both m-tiles ----
        float s0[8][4], s1[8][4];
#pragma unroll
        for (int n = 0; n < 8; n++) {
            s0[n][0]=s0[n][1]=s0[n][2]=s0[n][3]=0.f;
            s1[n][0]=s1[n][1]=s1[n][2]=s1[n][3]=0.f;
            const unsigned* krow = &Kf[(n*8 + lq)*KS_STR + 4*lr];
#pragma unroll
            for (int kkp = 0; kkp < 4; kkp++) {
                uint4 kb = *(const uint4*)(krow + kkp*16);
                mma8(s0[n], qf[0][2*kkp],   kb.x, kb.y);
                mma8(s0[n], qf[0][2*kkp+1], kb.z, kb.w);
                mma8(s1[n], qf[1][2*kkp],   kb.x, kb.y);
                mma8(s1[n], qf[1][2*kkp+1], kb.z, kb.w);
            }
        }

        // ---- online softmax in exp2 domain ----
        float mA=-1e30f, mB=-1e30f, mC=-1e30f, mD=-1e30f;
#pragma unroll
        for (int n = 0; n < 8; n++) {
            mA = fmaxf(mA, fmaxf(s0[n][0], s0[n][1]));
            mB = fmaxf(mB, fmaxf(s0[n][2], s0[n][3]));
            mC = fmaxf(mC, fmaxf(s1[n][0], s1[n][1]));
            mD = fmaxf(mD, fmaxf(s1[n][2], s1[n][3]));
        }
        mA = fmaxf(mA, __shfl_xor_sync(0xffffffffu, mA, 1));
        mA = fmaxf(mA, __shfl_xor_sync(0xffffffffu, mA, 2));
        mB = fmaxf(mB, __shfl_xor_sync(0xffffffffu, mB, 1));
        mB = fmaxf(mB, __shfl_xor_sync(0xffffffffu, mB, 2));
        mC = fmaxf(mC, __shfl_xor_sync(0xffffffffu, mC, 1));
        mC = fmaxf(mC, __shfl_xor_sync(0xffffffffu, mC, 2));
        mD = fmaxf(mD, __shfl_xor_sync(0xffffffffu, mD, 1));
        mD = fmaxf(mD, __shfl_xor_sync(0xffffffffu, mD, 2));
        float mnA = fmaxf(mst[0], mA), mnB = fmaxf(mst[1], mB);
        float mnC = fmaxf(mst[2], mC), mnD = fmaxf(mst[3], mD);
        float cA = exp2f(mst[0]-mnA), cB = exp2f(mst[1]-mnB);
        float cC = exp2f(mst[2]-mnC), cD = exp2f(mst[3]-mnD);
        float sA=0.f, sB=0.f, sC=0.f, sD=0.f;
#pragma unroll
        for (int n = 0; n < 8; n++) {
            s0[n][0] = exp2f(s0[n][0]-mnA); s0[n][1] = exp2f(s0[n][1]-mnA);
            s0[n][2] = exp2f(s0[n][2]-mnB); s0[n][3] = exp2f(s0[n][3]-mnB);
            s1[n][0] = exp2f(s1[n][0]-mnC); s1[n][1] = exp2f(s1[n][1]-mnC);
            s1[n][2] = exp2f(s1[n][2]-mnD); s1[n][3] = exp2f(s1[n][3]-mnD);
            sA += s0[n][0]+s0[n][1]; sB += s0[n][2]+s0[n][3];
            sC += s1[n][0]+s1[n][1]; sD += s1[n][2]+s1[n][3];
        }
        sA += __shfl_xor_sync(0xffffffffu, sA, 1);
        sA += __shfl_xor_sync(0xffffffffu, sA, 2);
        sB += __shfl_xor_sync(0xffffffffu, sB, 1);
        sB += __shfl_xor_sync(0xffffffffu, sB, 2);
        sC += __shfl_xor_sync(0xffffffffu, sC, 1);
        sC += __shfl_xor_sync(0xffffffffu, sC, 2);
        sD += __shfl_xor_sync(0xffffffffu, sD, 1);
        sD += __shfl_xor_sync(0xffffffffu, sD, 2);
        lst[0] = lst[0]*cA + sA; mst[0] = mnA;
        lst[1] = lst[1]*cB + sB; mst[1] = mnB;
        lst[2] = lst[2]*cC + sC; mst[2] = mnC;
        lst[3] = lst[3]*cD + sD; mst[3] = mnD;
#pragma unroll
        for (int n = 0; n < 8; n++) {
            O[0][n][0] *= cA; O[0][n][1] *= cA;
            O[0][n][2] *= cB; O[0][n][3] *= cB;
            O[1][n][0] *= cC; O[1][n][1] *= cC;
            O[1][n][2] *= cD; O[1][n][3] *= cD;
        }

        // ---- O += P V : P A-frags direct from registers ----
#pragma unroll
        for (int kk = 0; kk < 8; kk++) {
            unsigned pa0[4], pa1[4];
            pa0[0] = f2tf(s0[kk][0]); pa0[1] = f2tf(s0[kk][2]);
            pa0[2] = f2tf(s0[kk][1]); pa0[3] = f2tf(s0[kk][3]);
            pa1[0] = f2tf(s1[kk][0]); pa1[1] = f2tf(s1[kk][2]);
            pa1[2] = f2tf(s1[kk][1]); pa1[3] = f2tf(s1[kk][3]);
            const unsigned* vrow = &Vf[(kk*4 + lr)*VI_STR];
#pragma unroll
            for (int n = 0; n < 8; n++) {
                uint2 vb = *(const uint2*)(vrow + (n*8 + lq)*2);
                mma8(O[0][n], pa0, vb.x, vb.y);
                mma8(O[1][n], pa1, vb.x, vb.y);
            }
        }

        __syncthreads();
        if (kt + 2 < NKT) issueKV(kt + 2, s);
    }

    // epilogue: normalize, tf32-round, d-perm store into g_att
    float iA = 1.f/lst[0], iB = 1.f/lst[1], iC = 1.f/lst[2], iD = 1.f/lst[3];
    int rowA = qt*128 + r0 + lq;
#pragma unroll
    for (int n = 0; n < 8; n++) {
        int col = h*HDIM + n*8 + pp;
        size_t b0 = (size_t)(b*NTOK + rowA)*D_MODEL + col;
        size_t b1 = (size_t)(b*NTOK + rowA + 8)*D_MODEL + col;
        size_t b2 = (size_t)(b*NTOK + rowA + 16)*D_MODEL + col;
        size_t b3 = (size_t)(b*NTOK + rowA + 24)*D_MODEL + col;
        g_att[b0]     = f2tf(O[0][n][0]*iA);
        g_att[b0 + 2] = f2tf(O[0][n][1]*iA);
        g_att[b1]     = f2tf(O[0][n][2]*iB);
        g_att[b1 + 2] = f2tf(O[0][n][3]*iB);
        g_att[b2]     = f2tf(O[1][n][0]*iC);
        g_att[b2 + 2] = f2tf(O[1][n][1]*iC);
        g_att[b3]     = f2tf(O[1][n][2]*iD);
        g_att[b3 + 2] = f2tf(O[1][n][3]*iD);
    }
}

// ============================================================
// launch
// ============================================================
extern "C" void kernel_launch(void* const* d_in, const int* in_sizes, int n_in,
                              void* d_out, int out_size) {
    const float* x      = (const float*)d_in[0];
    const float* w_qkv  = (const float*)d_in[1];
    const float* b_qkv  = (const float*)d_in[2];
    const float* w_proj = (const float*)d_in[3];
    const float* b_proj = (const float*)d_in[4];
    float* out = (float*)d_out;
    (void)in_sizes; (void)n_in; (void)out_size;

    rope_tables_kernel<<<(NTOK*HDIM)/256, 256>>>();

    const int NCONV = MROWS*D_MODEL/4 + (D_MODEL/8*4)*(QKVCOLS/4) + (D_MODEL/8*4)*(D_MODEL/4);
    preconvert_kernel<<<(NCONV + 255)/256, 256>>>(x, w_qkv, w_proj);

    cudaFuncSetAttribute(gemm_tf32_kernel<QKVCOLS, true, 128>,
                         cudaFuncAttributeMaxDynamicSharedMemorySize, GEMM_SMEM(128));
    gemm_tf32_kernel<QKVCOLS, true, 128>
        <<<dim3(QKVCOLS/128, MROWS/128), 256, GEMM_SMEM(128)>>>(b_qkv, nullptr);

    cudaFuncSetAttribute(flash_tf32_kernel,
                         cudaFuncAttributeMaxDynamicSharedMemorySize, FLASH_SMEM);
    flash_tf32_kernel<<<dim3(NTOK/128, BATCH*NHEADS), 128, FLASH_SMEM>>>();

    cudaFuncSetAttribute(gemm_tf32_kernel<D_MODEL, false, 64>,
                         cudaFuncAttributeMaxDynamicSharedMemorySize, GEMM_SMEM(64));
    gemm_tf32_kernel<D_MODEL, false, 64>
        <<<dim3(D_MODEL/128, MROWS/64), 256, GEMM_SMEM(64)>>>(b_proj, out);
}